// round 2
// baseline (speedup 1.0000x reference)
#include <cuda_runtime.h>
#include <cuda_bf16.h>

// Problem constants (fixed by the reference)
#define NB   1024      // batch
#define NS1  25        // hop-1 fanout
#define NS2  10        // hop-2 fanout
#define ND   256       // feature dim
#define NH   128       // per-branch hidden
#define NC   64        // classes
#define M1   (NB*NS1)  // 25600

// Scratch (no cudaMalloc allowed -> __device__ globals)
__device__ float g_g1[M1 * ND];   // layer-1 output on hop-1 set [25600,256]
__device__ float g_g0[NB * ND];   // layer-1 output on batch set [1024,256]
__device__ float g_f0[NB * ND];   // layer-2 output              [1024,256]

// ---------------------------------------------------------------------------
// Fused gather-mean GEMM tile body.
//   C[m0+m, colOff : colOff+128] = act( Arow(m) @ W[256,128] + bias )
//   Arow(m) = (1/F) * sum_{s<F} Asrc[ row(m,s) ]  where
//   row(m,s) = HAS_IDS ? ids[(m0+m)*F + s] : (m0+m)*F + s
// Tile: 128 rows x 128 cols, BK=32, 256 threads, 8x8 micro-tile.
// ---------------------------------------------------------------------------
template<int F, bool HAS_IDS, bool RELU>
__device__ __forceinline__ void gemm_body(
    float* __restrict__ As,          // smem [32][132]
    float* __restrict__ Bs,          // smem [32][128]
    int*   __restrict__ ids_s,       // smem [128*F] (HAS_IDS only)
    const float* __restrict__ Asrc,
    const int*   __restrict__ ids,
    const float* __restrict__ W,
    const float* __restrict__ bias,
    float* __restrict__ C, int colOff)
{
    const int m0 = blockIdx.x * 128;
    const int t  = threadIdx.x;

    if (HAS_IDS) {
        for (int j = t; j < 128 * F; j += 256)
            ids_s[j] = ids[(size_t)m0 * F + j];
        __syncthreads();
    }

    const int tx   = t & 15;          // 16 thread cols
    const int ty   = t >> 4;          // 16 thread rows
    const int row0 = ty * 8;
    const int col0 = tx * 8;
    const int kq   = t >> 5;          // 0..7 : k-quad for A fill (k base 4*kq)
    const int ml   = t & 31;          // m lane for A fill

    float acc[8][8];
    #pragma unroll
    for (int i = 0; i < 8; ++i)
        #pragma unroll
        for (int j = 0; j < 8; ++j) acc[i][j] = 0.f;

    constexpr float inv = 1.0f / (float)F;

    for (int k0 = 0; k0 < ND; k0 += 32) {
        // ---- B tile: Bs[k][n], coalesced (warp = one k row, 512B) ----
        {
            const int n4 = (t & 31) * 4;
            const int kk = t >> 5;
            #pragma unroll
            for (int p = 0; p < 4; ++p) {
                int k = kk + p * 8;
                *(float4*)&Bs[k * 128 + n4] =
                    *(const float4*)&W[(size_t)(k0 + k) * NH + n4];
            }
        }
        // ---- A tile: gather-mean of F source rows, transposed into As ----
        #pragma unroll
        for (int i = 0; i < 4; ++i) {
            const int m = ml + i * 32;
            float4 v = make_float4(0.f, 0.f, 0.f, 0.f);
            #pragma unroll
            for (int s = 0; s < F; ++s) {
                int row;
                if (HAS_IDS) row = ids_s[m * F + s];
                else         row = (m0 + m) * F + s;
                float4 u = *(const float4*)&Asrc[(size_t)row * ND + k0 + 4 * kq];
                v.x += u.x; v.y += u.y; v.z += u.z; v.w += u.w;
            }
            if (F > 1) { v.x *= inv; v.y *= inv; v.z *= inv; v.w *= inv; }
            // conflict-free: warp has fixed kq, m covers all 32 banks
            As[(4 * kq + 0) * 132 + m] = v.x;
            As[(4 * kq + 1) * 132 + m] = v.y;
            As[(4 * kq + 2) * 132 + m] = v.z;
            As[(4 * kq + 3) * 132 + m] = v.w;
        }
        __syncthreads();

        // ---- 8x8 FMA micro-kernel ----
        #pragma unroll
        for (int k = 0; k < 32; ++k) {
            float4 a0 = *(const float4*)&As[k * 132 + row0];
            float4 a1 = *(const float4*)&As[k * 132 + row0 + 4];
            float4 b0 = *(const float4*)&Bs[k * 128 + col0];
            float4 b1 = *(const float4*)&Bs[k * 128 + col0 + 4];
            float av[8] = {a0.x, a0.y, a0.z, a0.w, a1.x, a1.y, a1.z, a1.w};
            float bv[8] = {b0.x, b0.y, b0.z, b0.w, b1.x, b1.y, b1.z, b1.w};
            #pragma unroll
            for (int i = 0; i < 8; ++i)
                #pragma unroll
                for (int j = 0; j < 8; ++j)
                    acc[i][j] = fmaf(av[i], bv[j], acc[i][j]);
        }
        __syncthreads();
    }

    // ---- epilogue: bias (+relu), vectorized store into concat output ----
    float bb[8];
    #pragma unroll
    for (int j = 0; j < 8; ++j) bb[j] = bias[col0 + j];

    #pragma unroll
    for (int i = 0; i < 8; ++i) {
        float v[8];
        #pragma unroll
        for (int j = 0; j < 8; ++j) {
            float x = acc[i][j] + bb[j];
            v[j] = RELU ? fmaxf(x, 0.f) : x;
        }
        float* dst = &C[(size_t)(m0 + row0 + i) * ND + colOff + col0];
        *(float4*)(dst)     = make_float4(v[0], v[1], v[2], v[3]);
        *(float4*)(dst + 4) = make_float4(v[4], v[5], v[6], v[7]);
    }
}

// ---------------------------------------------------------------------------
// Layer 1: all four independent branch GEMMs in one launch. grid (200, 4).
//   y=0: g1[:,0:128]   = relu(feat[ids1]        @ Wx1 + bx1)   M=25600
//   y=1: g1[:,128:256] = relu(mean10(feat[ids2])@ Wn1 + bn1)   M=25600
//   y=2: g0[:,0:128]   = relu(feat[ids0]        @ Wx1 + bx1)   M=1024
//   y=3: g0[:,128:256] = relu(mean25(feat[ids1])@ Wn1 + bn1)   M=1024
// ---------------------------------------------------------------------------
__global__ void __launch_bounds__(256, 2) layer1_kernel(
    const float* __restrict__ feat,
    const int* __restrict__ ids0, const int* __restrict__ ids1,
    const int* __restrict__ ids2,
    const float* __restrict__ Wx1, const float* __restrict__ bx1,
    const float* __restrict__ Wn1, const float* __restrict__ bn1,
    float* __restrict__ g1, float* __restrict__ g0)
{
    __shared__ float As[32 * 132];
    __shared__ float Bs[32 * 128];
    __shared__ int   ids_s[128 * 25];

    switch (blockIdx.y) {
    case 0:
        gemm_body<1, true, true>(As, Bs, ids_s, feat, ids1, Wx1, bx1, g1, 0);
        break;
    case 1:
        gemm_body<10, true, true>(As, Bs, ids_s, feat, ids2, Wn1, bn1, g1, NH);
        break;
    case 2:
        if (blockIdx.x < NB / 128)
            gemm_body<1, true, true>(As, Bs, ids_s, feat, ids0, Wx1, bx1, g0, 0);
        break;
    default:
        if (blockIdx.x < NB / 128)
            gemm_body<25, true, true>(As, Bs, ids_s, feat, ids1, Wn1, bn1, g0, NH);
        break;
    }
}

// ---------------------------------------------------------------------------
// Layer 2 (no activation). grid (8, 2).
//   y=0: f0[:,0:128]   = g0        @ Wx2 + bx2
//   y=1: f0[:,128:256] = mean25(g1)@ Wn2 + bn2   (mean fused, no gm buffer)
// ---------------------------------------------------------------------------
__global__ void __launch_bounds__(256, 2) layer2_kernel(
    const float* __restrict__ g0, const float* __restrict__ g1,
    const float* __restrict__ Wx2, const float* __restrict__ bx2,
    const float* __restrict__ Wn2, const float* __restrict__ bn2,
    float* __restrict__ f0)
{
    __shared__ float As[32 * 132];
    __shared__ float Bs[32 * 128];

    if (blockIdx.y == 0)
        gemm_body<1, false, false>(As, Bs, nullptr, g0, nullptr, Wx2, bx2, f0, 0);
    else
        gemm_body<25, false, false>(As, Bs, nullptr, g1, nullptr, Wn2, bn2, f0, NH);
}

// ---------------------------------------------------------------------------
// out[b, c] = f0[b,:256] @ Wfc[256,64] + bfc    (4 batch rows per block)
// ---------------------------------------------------------------------------
__global__ void __launch_bounds__(256) out_head(
    const float* __restrict__ f0, const float* __restrict__ Wfc,
    const float* __restrict__ bfc, float* __restrict__ out)
{
    __shared__ float rows[4][ND];
    const int b0 = blockIdx.x * 4;
    const int t  = threadIdx.x;
    #pragma unroll
    for (int i = 0; i < 4; ++i)
        rows[i][t] = f0[(size_t)(b0 + i) * ND + t];
    __syncthreads();

    const int r = t >> 6;      // 0..3
    const int c = t & 63;      // 0..63
    float acc = bfc[c];
    #pragma unroll 8
    for (int k = 0; k < ND; ++k)
        acc = fmaf(rows[r][k], Wfc[(size_t)k * NC + c], acc);
    out[(size_t)(b0 + r) * NC + c] = acc;
}

// ---------------------------------------------------------------------------
extern "C" void kernel_launch(void* const* d_in, const int* in_sizes, int n_in,
                              void* d_out, int out_size)
{
    const int*   ids0 = (const int*)  d_in[0];
    const int*   ids1 = (const int*)  d_in[1];
    const int*   ids2 = (const int*)  d_in[2];
    const float* feat = (const float*)d_in[3];
    const float* Wx1  = (const float*)d_in[4];
    const float* bx1  = (const float*)d_in[5];
    const float* Wn1  = (const float*)d_in[6];
    const float* bn1  = (const float*)d_in[7];
    const float* Wx2  = (const float*)d_in[8];
    const float* bx2  = (const float*)d_in[9];
    const float* Wn2  = (const float*)d_in[10];
    const float* bn2  = (const float*)d_in[11];
    const float* Wfc  = (const float*)d_in[12];
    const float* bfc  = (const float*)d_in[13];
    float* out = (float*)d_out;

    float *g1, *g0, *f0;
    cudaGetSymbolAddress((void**)&g1, g_g1);
    cudaGetSymbolAddress((void**)&g0, g_g0);
    cudaGetSymbolAddress((void**)&f0, g_f0);

    // Layer 1: all 4 branch GEMMs, gathers + means fused. grid (200,4).
    layer1_kernel<<<dim3(M1 / 128, 4), 256>>>(
        feat, ids0, ids1, ids2, Wx1, bx1, Wn1, bn1, g1, g0);

    // Layer 2: both halves, mean over S1 fused. grid (8,2).
    layer2_kernel<<<dim3(NB / 128, 2), 256>>>(
        g0, g1, Wx2, bx2, Wn2, bn2, f0);

    // Head.
    out_head<<<NB / 4, 256>>>(f0, Wfc, bfc, out);
}

// round 3
// speedup vs baseline: 2.2365x; 2.2365x over previous
#include <cuda_runtime.h>
#include <cuda_bf16.h>

// Problem constants (fixed by the reference)
#define NB   1024      // batch
#define NS1  25        // hop-1 fanout
#define NS2  10        // hop-2 fanout
#define ND   256       // feature dim
#define NH   128       // per-branch hidden
#define NC   64        // classes
#define M1   (NB*NS1)  // 25600

// Scratch (no cudaMalloc allowed -> __device__ globals)
__device__ float g_m1[M1 * ND];   // mean over S2 of hop-2 feats   [25600,256]
__device__ float g_m0[NB * ND];   // mean over S1 of hop-1 feats   [1024,256]
__device__ float g_g1[M1 * ND];   // layer-1 out, hop-1 set        [25600,256]
__device__ float g_g0[NB * ND];   // layer-1 out, batch set        [1024,256]
__device__ float g_gm[NB * ND];   // mean over S1 of g1            [1024,256]
__device__ float g_f0[NB * ND];   // layer-2 out                   [1024,256]

// ---------------------------------------------------------------------------
// float4 gather-mean: dst[g,:] = (1/F) * sum_{s<F} src[row(g,s),:]
// 64 threads per group (float4 per thread), 4 groups per 256-thread block.
// ---------------------------------------------------------------------------
__device__ __forceinline__ void mean_body(
    const float* __restrict__ src, const int* __restrict__ ids,
    float* __restrict__ dst, int g, int F, float inv)
{
    const int c = (threadIdx.x & 63) * 4;
    float4 acc = make_float4(0.f, 0.f, 0.f, 0.f);
    const long base = (long)g * F;
    for (int s = 0; s < F; ++s) {
        int row = ids ? ids[base + s] : (int)(base + s);
        float4 u = *(const float4*)&src[(size_t)row * ND + c];
        acc.x += u.x; acc.y += u.y; acc.z += u.z; acc.w += u.w;
    }
    acc.x *= inv; acc.y *= inv; acc.z *= inv; acc.w *= inv;
    *(float4*)&dst[(size_t)g * ND + c] = acc;
}

// hop-2 mean (25600 groups, F=10) and hop-1 mean (1024 groups, F=25), fused.
__global__ void __launch_bounds__(256) means_kernel(
    const float* __restrict__ feat,
    const int* __restrict__ ids1, const int* __restrict__ ids2,
    float* __restrict__ m1, float* __restrict__ m0)
{
    const int sub = threadIdx.x >> 6;   // 0..3 group within block
    if (blockIdx.x < M1 / 4) {
        mean_body(feat, ids2, m1, blockIdx.x * 4 + sub, NS2, 1.0f / NS2);
    } else {
        int g = (blockIdx.x - M1 / 4) * 4 + sub;
        mean_body(feat, ids1, m0, g, NS1, 1.0f / NS1);
    }
}

// g1 mean (1024 groups, F=25, dense)
__global__ void __launch_bounds__(256) g1mean_kernel(
    const float* __restrict__ g1, float* __restrict__ gm)
{
    mean_body(g1, nullptr, gm, blockIdx.x * 4 + (threadIdx.x >> 6), NS1,
              1.0f / NS1);
}

// ---------------------------------------------------------------------------
// 128x128 tile GEMM, BK=32, 256 threads, 8x8 micro-tile, register-staged
// pipeline. A rows optionally gathered through ids (single indirection).
//   C[mbase+m, colOff:colOff+128] = act( A[m,:256] @ W[256,128] + bias )
// ---------------------------------------------------------------------------
template<bool HAS_IDS, bool RELU>
__device__ __forceinline__ void gemm128(
    float* __restrict__ As,              // smem [32][132]
    float* __restrict__ Bs,              // smem [32][128]
    const float* __restrict__ Asrc, const int* __restrict__ ids,
    const float* __restrict__ W, const float* __restrict__ bias,
    float* __restrict__ C, int colOff, int mbase)
{
    const int t  = threadIdx.x;
    const int kq = t >> 5;               // 0..7  (k quad: k base = 4*kq)
    const int ml = t & 31;               // m lane

    // A source row pointers (gather resolved once)
    const float* aptr[4];
    #pragma unroll
    for (int i = 0; i < 4; ++i) {
        int m = ml + i * 32;
        int row = HAS_IDS ? ids[mbase + m] : (mbase + m);
        aptr[i] = Asrc + (size_t)row * ND + 4 * kq;
    }
    // B source pointer: slot p -> k = kq + p*8, n = (t&31)*4
    const float* bptr = W + (size_t)(t >> 5) * NH + (t & 31) * 4;

    float acc[8][8];
    #pragma unroll
    for (int i = 0; i < 8; ++i)
        #pragma unroll
        for (int j = 0; j < 8; ++j) acc[i][j] = 0.f;

    float4 areg[4], breg[4];
    #pragma unroll
    for (int i = 0; i < 4; ++i) areg[i] = *(const float4*)(aptr[i]);
    #pragma unroll
    for (int p = 0; p < 4; ++p)
        breg[p] = *(const float4*)(bptr + (size_t)(p * 8) * NH);

    const int row0 = (t >> 4) * 8;
    const int col0 = (t & 15) * 8;

    #pragma unroll 1
    for (int c0 = 0; c0 < 8; ++c0) {
        // ---- stage regs -> smem ----
        #pragma unroll
        for (int i = 0; i < 4; ++i) {
            const int m = ml + i * 32;          // warp: 32 banks, no conflict
            As[(4 * kq + 0) * 132 + m] = areg[i].x;
            As[(4 * kq + 1) * 132 + m] = areg[i].y;
            As[(4 * kq + 2) * 132 + m] = areg[i].z;
            As[(4 * kq + 3) * 132 + m] = areg[i].w;
        }
        #pragma unroll
        for (int p = 0; p < 4; ++p)
            *(float4*)&Bs[(kq + p * 8) * 128 + (t & 31) * 4] = breg[p];
        __syncthreads();

        // ---- prefetch next chunk ----
        if (c0 < 7) {
            const int koff = (c0 + 1) * 32;
            #pragma unroll
            for (int i = 0; i < 4; ++i)
                areg[i] = *(const float4*)(aptr[i] + koff);
            #pragma unroll
            for (int p = 0; p < 4; ++p)
                breg[p] = *(const float4*)(bptr + (size_t)(koff + p * 8) * NH);
        }

        // ---- 8x8 FMA micro-kernel over 32 k ----
        #pragma unroll
        for (int k = 0; k < 32; ++k) {
            float4 a0 = *(const float4*)&As[k * 132 + row0];
            float4 a1 = *(const float4*)&As[k * 132 + row0 + 4];
            float4 b0 = *(const float4*)&Bs[k * 128 + col0];
            float4 b1 = *(const float4*)&Bs[k * 128 + col0 + 4];
            float av[8] = {a0.x, a0.y, a0.z, a0.w, a1.x, a1.y, a1.z, a1.w};
            float bv[8] = {b0.x, b0.y, b0.z, b0.w, b1.x, b1.y, b1.z, b1.w};
            #pragma unroll
            for (int i = 0; i < 8; ++i)
                #pragma unroll
                for (int j = 0; j < 8; ++j)
                    acc[i][j] = fmaf(av[i], bv[j], acc[i][j]);
        }
        __syncthreads();
    }

    // ---- epilogue ----
    float bb[8];
    #pragma unroll
    for (int j = 0; j < 8; ++j) bb[j] = bias[col0 + j];

    #pragma unroll
    for (int i = 0; i < 8; ++i) {
        float v[8];
        #pragma unroll
        for (int j = 0; j < 8; ++j) {
            float x = acc[i][j] + bb[j];
            v[j] = RELU ? fmaxf(x, 0.f) : x;
        }
        float* dst = &C[(size_t)(mbase + row0 + i) * ND + colOff + col0];
        *(float4*)(dst)     = make_float4(v[0], v[1], v[2], v[3]);
        *(float4*)(dst + 4) = make_float4(v[4], v[5], v[6], v[7]);
    }
}

// ---------------------------------------------------------------------------
// Layer 1: all four branch GEMMs. grid (208, 2).
//  y=0,x<200 : g1[:,0:128]   = relu(feat[ids1] @ Wx1 + bx1)
//  y=0,x>=200: g0[:,0:128]   = relu(feat[ids0] @ Wx1 + bx1)
//  y=1,x<200 : g1[:,128:256] = relu(m1 @ Wn1 + bn1)
//  y=1,x>=200: g0[:,128:256] = relu(m0 @ Wn1 + bn1)
// ---------------------------------------------------------------------------
__global__ void __launch_bounds__(256, 2) layer1_kernel(
    const float* __restrict__ feat,
    const int* __restrict__ ids0, const int* __restrict__ ids1,
    const float* __restrict__ m1, const float* __restrict__ m0,
    const float* __restrict__ Wx1, const float* __restrict__ bx1,
    const float* __restrict__ Wn1, const float* __restrict__ bn1,
    float* __restrict__ g1, float* __restrict__ g0)
{
    __shared__ float As[32 * 132];
    __shared__ float Bs[32 * 128];
    const int x = blockIdx.x;

    if (blockIdx.y == 0) {
        if (x < 200)
            gemm128<true, true>(As, Bs, feat, ids1, Wx1, bx1, g1, 0, x * 128);
        else
            gemm128<true, true>(As, Bs, feat, ids0, Wx1, bx1, g0, 0,
                                (x - 200) * 128);
    } else {
        if (x < 200)
            gemm128<false, true>(As, Bs, m1, nullptr, Wn1, bn1, g1, NH,
                                 x * 128);
        else
            gemm128<false, true>(As, Bs, m0, nullptr, Wn1, bn1, g0, NH,
                                 (x - 200) * 128);
    }
}

// Layer 2 (no activation). grid (8, 2).
__global__ void __launch_bounds__(256, 2) layer2_kernel(
    const float* __restrict__ g0, const float* __restrict__ gm,
    const float* __restrict__ Wx2, const float* __restrict__ bx2,
    const float* __restrict__ Wn2, const float* __restrict__ bn2,
    float* __restrict__ f0)
{
    __shared__ float As[32 * 132];
    __shared__ float Bs[32 * 128];
    if (blockIdx.y == 0)
        gemm128<false, false>(As, Bs, g0, nullptr, Wx2, bx2, f0, 0,
                              blockIdx.x * 128);
    else
        gemm128<false, false>(As, Bs, gm, nullptr, Wn2, bn2, f0, NH,
                              blockIdx.x * 128);
}

// ---------------------------------------------------------------------------
// out[b, c] = f0[b,:256] @ Wfc[256,64] + bfc    (4 batch rows per block)
// ---------------------------------------------------------------------------
__global__ void __launch_bounds__(256) out_head(
    const float* __restrict__ f0, const float* __restrict__ Wfc,
    const float* __restrict__ bfc, float* __restrict__ out)
{
    __shared__ float rows[4][ND];
    const int b0 = blockIdx.x * 4;
    const int t  = threadIdx.x;
    #pragma unroll
    for (int i = 0; i < 4; ++i)
        rows[i][t] = f0[(size_t)(b0 + i) * ND + t];
    __syncthreads();

    const int r = t >> 6;      // 0..3
    const int c = t & 63;      // 0..63
    float acc = bfc[c];
    #pragma unroll 8
    for (int k = 0; k < ND; ++k)
        acc = fmaf(rows[r][k], Wfc[(size_t)k * NC + c], acc);
    out[(size_t)(b0 + r) * NC + c] = acc;
}

// ---------------------------------------------------------------------------
extern "C" void kernel_launch(void* const* d_in, const int* in_sizes, int n_in,
                              void* d_out, int out_size)
{
    const int*   ids0 = (const int*)  d_in[0];
    const int*   ids1 = (const int*)  d_in[1];
    const int*   ids2 = (const int*)  d_in[2];
    const float* feat = (const float*)d_in[3];
    const float* Wx1  = (const float*)d_in[4];
    const float* bx1  = (const float*)d_in[5];
    const float* Wn1  = (const float*)d_in[6];
    const float* bn1  = (const float*)d_in[7];
    const float* Wx2  = (const float*)d_in[8];
    const float* bx2  = (const float*)d_in[9];
    const float* Wn2  = (const float*)d_in[10];
    const float* bn2  = (const float*)d_in[11];
    const float* Wfc  = (const float*)d_in[12];
    const float* bfc  = (const float*)d_in[13];
    float* out = (float*)d_out;

    float *m1, *m0, *g1, *g0, *gm, *f0;
    cudaGetSymbolAddress((void**)&m1, g_m1);
    cudaGetSymbolAddress((void**)&m0, g_m0);
    cudaGetSymbolAddress((void**)&g1, g_g1);
    cudaGetSymbolAddress((void**)&g0, g_g0);
    cudaGetSymbolAddress((void**)&gm, g_gm);
    cudaGetSymbolAddress((void**)&f0, g_f0);

    // 1) hop-2 + hop-1 gather means (streaming, bandwidth-bound)
    means_kernel<<<M1 / 4 + NB / 4, 256>>>(feat, ids1, ids2, m1, m0);

    // 2) layer 1: all four branch GEMMs in one launch
    layer1_kernel<<<dim3(208, 2), 256>>>(
        feat, ids0, ids1, m1, m0, Wx1, bx1, Wn1, bn1, g1, g0);

    // 3) mean over S1 of g1
    g1mean_kernel<<<NB / 4, 256>>>(g1, gm);

    // 4) layer 2: both halves
    layer2_kernel<<<dim3(NB / 128, 2), 256>>>(g0, gm, Wx2, bx2, Wn2, bn2, f0);

    // 5) head
    out_head<<<NB / 4, 256>>>(f0, Wfc, bfc, out);
}

// round 4
// speedup vs baseline: 2.5531x; 1.1415x over previous
#include <cuda_runtime.h>
#include <cuda_bf16.h>

// Problem constants (fixed by the reference)
#define NB   1024      // batch
#define NS1  25        // hop-1 fanout
#define NS2  10        // hop-2 fanout
#define ND   256       // feature dim
#define NH   128       // per-branch hidden
#define NC   64        // classes
#define M1   (NB*NS1)  // 25600

// Scratch (no cudaMalloc allowed -> __device__ globals)
__device__ float g_m1[M1 * ND];   // mean over S2 of hop-2 feats   [25600,256]
__device__ float g_m0[NB * ND];   // mean over S1 of hop-1 feats   [1024,256]
__device__ float g_g1[M1 * ND];   // layer-1 out, hop-1 set        [25600,256]
__device__ float g_g0[NB * ND];   // layer-1 out, batch set        [1024,256]
__device__ float g_gm[NB * ND];   // mean over S1 of g1            [1024,256]

// ---------------------------------------------------------------------------
// Templated float4 gather-mean: dst[g,:] = (1/F)*sum_{s<F} src[row(g,s),:]
// 64 threads per group, ids preloaded -> F loads in flight (high MLP).
// ---------------------------------------------------------------------------
template<int F, bool HAS_IDS>
__device__ __forceinline__ void mean_body(
    const float* __restrict__ src, const int* __restrict__ ids,
    float* __restrict__ dst, int g)
{
    const int c = (threadIdx.x & 63) * 4;
    const long base = (long)g * F;
    int rows[F];
    #pragma unroll
    for (int s = 0; s < F; ++s)
        rows[s] = HAS_IDS ? ids[base + s] : (int)(base + s);
    float4 acc = make_float4(0.f, 0.f, 0.f, 0.f);
    #pragma unroll
    for (int s = 0; s < F; ++s) {
        float4 u = *(const float4*)&src[(size_t)rows[s] * ND + c];
        acc.x += u.x; acc.y += u.y; acc.z += u.z; acc.w += u.w;
    }
    constexpr float inv = 1.0f / (float)F;
    acc.x *= inv; acc.y *= inv; acc.z *= inv; acc.w *= inv;
    *(float4*)&dst[(size_t)g * ND + c] = acc;
}

// hop-2 mean (25600 groups, F=10) and hop-1 mean (1024 groups, F=25), fused.
__global__ void __launch_bounds__(256) means_kernel(
    const float* __restrict__ feat,
    const int* __restrict__ ids1, const int* __restrict__ ids2,
    float* __restrict__ m1, float* __restrict__ m0)
{
    const int sub = threadIdx.x >> 6;   // 0..3 group within block
    if (blockIdx.x < M1 / 4)
        mean_body<NS2, true>(feat, ids2, m1, blockIdx.x * 4 + sub);
    else
        mean_body<NS1, true>(feat, ids1, m0, (blockIdx.x - M1 / 4) * 4 + sub);
}

// g1 mean (1024 groups, F=25, dense rows)
__global__ void __launch_bounds__(256) g1mean_kernel(
    const float* __restrict__ g1, float* __restrict__ gm)
{
    mean_body<NS1, false>(g1, nullptr, gm,
                          blockIdx.x * 4 + (threadIdx.x >> 6));
}

// ---------------------------------------------------------------------------
// 128x128 tile GEMM, BK=32, 256 threads, 8x8 micro-tile, register-staged
// pipeline. A rows optionally gathered through ids (single indirection).
//   C[mbase+m, colOff:colOff+128] = act( A[m,:256] @ W[256,128] + bias )
// ---------------------------------------------------------------------------
template<bool HAS_IDS, bool RELU>
__device__ __forceinline__ void gemm128(
    float* __restrict__ As,              // smem [32][132]
    float* __restrict__ Bs,              // smem [32][128]
    const float* __restrict__ Asrc, const int* __restrict__ ids,
    const float* __restrict__ W, const float* __restrict__ bias,
    float* __restrict__ C, int colOff, int mbase)
{
    const int t  = threadIdx.x;
    const int kq = t >> 5;               // 0..7  (k quad: k base = 4*kq)
    const int ml = t & 31;               // m lane

    const float* aptr[4];
    #pragma unroll
    for (int i = 0; i < 4; ++i) {
        int m = ml + i * 32;
        int row = HAS_IDS ? ids[mbase + m] : (mbase + m);
        aptr[i] = Asrc + (size_t)row * ND + 4 * kq;
    }
    const float* bptr = W + (size_t)(t >> 5) * NH + (t & 31) * 4;

    float acc[8][8];
    #pragma unroll
    for (int i = 0; i < 8; ++i)
        #pragma unroll
        for (int j = 0; j < 8; ++j) acc[i][j] = 0.f;

    float4 areg[4], breg[4];
    #pragma unroll
    for (int i = 0; i < 4; ++i) areg[i] = *(const float4*)(aptr[i]);
    #pragma unroll
    for (int p = 0; p < 4; ++p)
        breg[p] = *(const float4*)(bptr + (size_t)(p * 8) * NH);

    const int row0 = (t >> 4) * 8;
    const int col0 = (t & 15) * 8;

    #pragma unroll 1
    for (int c0 = 0; c0 < 8; ++c0) {
        #pragma unroll
        for (int i = 0; i < 4; ++i) {
            const int m = ml + i * 32;
            As[(4 * kq + 0) * 132 + m] = areg[i].x;
            As[(4 * kq + 1) * 132 + m] = areg[i].y;
            As[(4 * kq + 2) * 132 + m] = areg[i].z;
            As[(4 * kq + 3) * 132 + m] = areg[i].w;
        }
        #pragma unroll
        for (int p = 0; p < 4; ++p)
            *(float4*)&Bs[(kq + p * 8) * 128 + (t & 31) * 4] = breg[p];
        __syncthreads();

        if (c0 < 7) {
            const int koff = (c0 + 1) * 32;
            #pragma unroll
            for (int i = 0; i < 4; ++i)
                areg[i] = *(const float4*)(aptr[i] + koff);
            #pragma unroll
            for (int p = 0; p < 4; ++p)
                breg[p] = *(const float4*)(bptr + (size_t)(koff + p * 8) * NH);
        }

        #pragma unroll
        for (int k = 0; k < 32; ++k) {
            float4 a0 = *(const float4*)&As[k * 132 + row0];
            float4 a1 = *(const float4*)&As[k * 132 + row0 + 4];
            float4 b0 = *(const float4*)&Bs[k * 128 + col0];
            float4 b1 = *(const float4*)&Bs[k * 128 + col0 + 4];
            float av[8] = {a0.x, a0.y, a0.z, a0.w, a1.x, a1.y, a1.z, a1.w};
            float bv[8] = {b0.x, b0.y, b0.z, b0.w, b1.x, b1.y, b1.z, b1.w};
            #pragma unroll
            for (int i = 0; i < 8; ++i)
                #pragma unroll
                for (int j = 0; j < 8; ++j)
                    acc[i][j] = fmaf(av[i], bv[j], acc[i][j]);
        }
        __syncthreads();
    }

    float bb[8];
    #pragma unroll
    for (int j = 0; j < 8; ++j) bb[j] = bias[col0 + j];

    #pragma unroll
    for (int i = 0; i < 8; ++i) {
        float v[8];
        #pragma unroll
        for (int j = 0; j < 8; ++j) {
            float x = acc[i][j] + bb[j];
            v[j] = RELU ? fmaxf(x, 0.f) : x;
        }
        float* dst = &C[(size_t)(mbase + row0 + i) * ND + colOff + col0];
        *(float4*)(dst)     = make_float4(v[0], v[1], v[2], v[3]);
        *(float4*)(dst + 4) = make_float4(v[4], v[5], v[6], v[7]);
    }
}

// ---------------------------------------------------------------------------
// Layer 1: all four branch GEMMs. grid (208, 2).
// ---------------------------------------------------------------------------
__global__ void __launch_bounds__(256, 2) layer1_kernel(
    const float* __restrict__ feat,
    const int* __restrict__ ids0, const int* __restrict__ ids1,
    const float* __restrict__ m1, const float* __restrict__ m0,
    const float* __restrict__ Wx1, const float* __restrict__ bx1,
    const float* __restrict__ Wn1, const float* __restrict__ bn1,
    float* __restrict__ g1, float* __restrict__ g0)
{
    __shared__ float As[32 * 132];
    __shared__ float Bs[32 * 128];
    const int x = blockIdx.x;

    if (blockIdx.y == 0) {
        if (x < 200)
            gemm128<true, true>(As, Bs, feat, ids1, Wx1, bx1, g1, 0, x * 128);
        else
            gemm128<true, true>(As, Bs, feat, ids0, Wx1, bx1, g0, 0,
                                (x - 200) * 128);
    } else {
        if (x < 200)
            gemm128<false, true>(As, Bs, m1, nullptr, Wn1, bn1, g1, NH,
                                 x * 128);
        else
            gemm128<false, true>(As, Bs, m0, nullptr, Wn1, bn1, g0, NH,
                                 (x - 200) * 128);
    }
}

// ---------------------------------------------------------------------------
// Fused layer2 + head. grid 64, 16-row tiles.
//   f0[m, 0:128]   = g0[m,:] @ Wx2 + bx2        (computed in-tile)
//   f0[m, 128:256] = gm[m,:] @ Wn2 + bn2
//   out[m, 0:64]   = f0[m,:] @ Wfc + bfc
// No f0 global buffer; f0 tile staged in shared memory.
// smem layout (floats):
//   As0 [32][20]  @ 0        (g0 k-tile, [k][row])
//   As1 [32][20]  @ 640      (gm k-tile)
//   Bs  [32][256] @ 1280     (Wx2|Wn2 k-tile, [k][n])
//   f0s [16][260] @ 1280     (aliases Bs after main loop)
//   Ws  [32][68]  @ 1280+4608 (Wfc k-tile for head)
// ---------------------------------------------------------------------------
#define L2R 16
__global__ void __launch_bounds__(256) layer2_head_kernel(
    const float* __restrict__ g0, const float* __restrict__ gm,
    const float* __restrict__ Wx2, const float* __restrict__ bx2,
    const float* __restrict__ Wn2, const float* __restrict__ bn2,
    const float* __restrict__ Wfc, const float* __restrict__ bfc,
    float* __restrict__ out)
{
    __shared__ float sm[1280 + 8320];
    float* As0 = sm;                 // [32][20]
    float* As1 = sm + 640;           // [32][20]
    float* Bs  = sm + 1280;          // [32][256]
    float* f0s = sm + 1280;          // [16][260] (alias)
    float* Ws  = sm + 1280 + 4608;   // [32][68]

    const int t  = threadIdx.x;
    const int m0 = blockIdx.x * L2R;

    // ---- main GEMM: f0 tile [16 x 256] ----
    const int trow = t >> 5;             // 8 row-groups x 2 rows
    const int tcol = t & 31;             // 32 col-groups x 8 cols
    const int r0   = trow * 2;
    const int col0 = tcol * 8;

    // A fill mapping: t<128 -> g0, t>=128 -> gm ; tt: row=tt&15, kq=tt>>4
    const int tt   = t & 127;
    const int arow = tt & 15;
    const int akq  = tt >> 4;
    const float* Aglob = (t < 128) ? g0 : gm;
    float* Asm = (t < 128) ? As0 : As1;
    const float* aptr = Aglob + (size_t)(m0 + arow) * ND + 4 * akq;

    float acc[2][8];
    #pragma unroll
    for (int i = 0; i < 2; ++i)
        #pragma unroll
        for (int j = 0; j < 8; ++j) acc[i][j] = 0.f;

    float4 areg = *(const float4*)(aptr);
    float4 breg[8];
    #pragma unroll
    for (int i = 0; i < 8; ++i) {
        int f4 = t + 256 * i;                    // 2048 float4 slots
        int k = f4 >> 6, n4 = (f4 & 63) * 4;
        const float* src = (n4 < 128) ? &Wx2[(size_t)k * NH + n4]
                                      : &Wn2[(size_t)k * NH + (n4 - 128)];
        breg[i] = *(const float4*)src;
    }

    const float* Asel = (col0 < 128) ? As0 : As1;

    #pragma unroll 1
    for (int c0 = 0; c0 < 8; ++c0) {
        // stage regs -> smem
        Asm[(4 * akq + 0) * 20 + arow] = areg.x;
        Asm[(4 * akq + 1) * 20 + arow] = areg.y;
        Asm[(4 * akq + 2) * 20 + arow] = areg.z;
        Asm[(4 * akq + 3) * 20 + arow] = areg.w;
        #pragma unroll
        for (int i = 0; i < 8; ++i) {
            int f4 = t + 256 * i;
            int k = f4 >> 6, n4 = (f4 & 63) * 4;
            *(float4*)&Bs[k * 256 + n4] = breg[i];
        }
        __syncthreads();

        // prefetch next chunk
        if (c0 < 7) {
            const int koff = (c0 + 1) * 32;
            areg = *(const float4*)(aptr + koff);
            #pragma unroll
            for (int i = 0; i < 8; ++i) {
                int f4 = t + 256 * i;
                int k = (f4 >> 6) + koff, n4 = (f4 & 63) * 4;
                const float* src = (n4 < 128)
                    ? &Wx2[(size_t)k * NH + n4]
                    : &Wn2[(size_t)k * NH + (n4 - 128)];
                breg[i] = *(const float4*)src;
            }
        }

        // 2x8 micro-kernel
        #pragma unroll
        for (int k = 0; k < 32; ++k) {
            float a0 = Asel[k * 20 + r0];
            float a1 = Asel[k * 20 + r0 + 1];
            float4 b0 = *(const float4*)&Bs[k * 256 + col0];
            float4 b1 = *(const float4*)&Bs[k * 256 + col0 + 4];
            float bv[8] = {b0.x, b0.y, b0.z, b0.w, b1.x, b1.y, b1.z, b1.w};
            #pragma unroll
            for (int j = 0; j < 8; ++j) {
                acc[0][j] = fmaf(a0, bv[j], acc[0][j]);
                acc[1][j] = fmaf(a1, bv[j], acc[1][j]);
            }
        }
        __syncthreads();
    }

    // ---- stage f0 tile (+bias) into smem ----
    #pragma unroll
    for (int j = 0; j < 8; ++j) {
        int n = col0 + j;
        float b = (n < 128) ? bx2[n] : bn2[n - 128];
        f0s[(r0 + 0) * 260 + n] = acc[0][j] + b;
        f0s[(r0 + 1) * 260 + n] = acc[1][j] + b;
    }
    __syncthreads();

    // ---- head: out[16 x 64] = f0s @ Wfc + bfc ----
    const int hr0 = (t >> 5) * 2;        // 8 groups x 2 rows
    const int hc0 = (t & 31) * 2;        // 32 groups x 2 cols
    float hacc[2][2] = {{0.f, 0.f}, {0.f, 0.f}};

    #pragma unroll 1
    for (int k0 = 0; k0 < ND; k0 += 32) {
        // stage Wfc chunk [32 x 64] -> Ws
        #pragma unroll
        for (int i = 0; i < 2; ++i) {
            int f4 = t + 256 * i;                // 512 float4 slots
            int k = f4 >> 4, c4 = (f4 & 15) * 4;
            *(float4*)&Ws[k * 68 + c4] =
                *(const float4*)&Wfc[(size_t)(k0 + k) * NC + c4];
        }
        __syncthreads();
        #pragma unroll
        for (int k = 0; k < 32; ++k) {
            float a0 = f0s[hr0 * 260 + k0 + k];
            float a1 = f0s[(hr0 + 1) * 260 + k0 + k];
            float w0 = Ws[k * 68 + hc0];
            float w1 = Ws[k * 68 + hc0 + 1];
            hacc[0][0] = fmaf(a0, w0, hacc[0][0]);
            hacc[0][1] = fmaf(a0, w1, hacc[0][1]);
            hacc[1][0] = fmaf(a1, w0, hacc[1][0]);
            hacc[1][1] = fmaf(a1, w1, hacc[1][1]);
        }
        __syncthreads();
    }

    float bf0 = bfc[hc0], bf1 = bfc[hc0 + 1];
    out[(size_t)(m0 + hr0) * NC + hc0]         = hacc[0][0] + bf0;
    out[(size_t)(m0 + hr0) * NC + hc0 + 1]     = hacc[0][1] + bf1;
    out[(size_t)(m0 + hr0 + 1) * NC + hc0]     = hacc[1][0] + bf0;
    out[(size_t)(m0 + hr0 + 1) * NC + hc0 + 1] = hacc[1][1] + bf1;
}

// ---------------------------------------------------------------------------
extern "C" void kernel_launch(void* const* d_in, const int* in_sizes, int n_in,
                              void* d_out, int out_size)
{
    const int*   ids0 = (const int*)  d_in[0];
    const int*   ids1 = (const int*)  d_in[1];
    const int*   ids2 = (const int*)  d_in[2];
    const float* feat = (const float*)d_in[3];
    const float* Wx1  = (const float*)d_in[4];
    const float* bx1  = (const float*)d_in[5];
    const float* Wn1  = (const float*)d_in[6];
    const float* bn1  = (const float*)d_in[7];
    const float* Wx2  = (const float*)d_in[8];
    const float* bx2  = (const float*)d_in[9];
    const float* Wn2  = (const float*)d_in[10];
    const float* bn2  = (const float*)d_in[11];
    const float* Wfc  = (const float*)d_in[12];
    const float* bfc  = (const float*)d_in[13];
    float* out = (float*)d_out;

    float *m1, *m0, *g1, *g0, *gm;
    cudaGetSymbolAddress((void**)&m1, g_m1);
    cudaGetSymbolAddress((void**)&m0, g_m0);
    cudaGetSymbolAddress((void**)&g1, g_g1);
    cudaGetSymbolAddress((void**)&g0, g_g0);
    cudaGetSymbolAddress((void**)&gm, g_gm);

    // 1) hop-2 + hop-1 gather means
    means_kernel<<<M1 / 4 + NB / 4, 256>>>(feat, ids1, ids2, m1, m0);

    // 2) layer 1: all four branch GEMMs
    layer1_kernel<<<dim3(208, 2), 256>>>(
        feat, ids0, ids1, m1, m0, Wx1, bx1, Wn1, bn1, g1, g0);

    // 3) mean over S1 of g1
    g1mean_kernel<<<NB / 4, 256>>>(g1, gm);

    // 4) fused layer 2 + head (no f0 buffer)
    layer2_head_kernel<<<NB / L2R, 256>>>(
        g0, gm, Wx2, bx2, Wn2, bn2, Wfc, bfc, out);
}

// round 5
// speedup vs baseline: 2.7972x; 1.0956x over previous
#include <cuda_runtime.h>
#include <cuda_bf16.h>

// Problem constants (fixed by the reference)
#define NB   1024      // batch
#define NS1  25        // hop-1 fanout
#define NS2  10        // hop-2 fanout
#define ND   256       // feature dim
#define NH   128       // per-branch hidden
#define NC   64        // classes
#define M1   (NB*NS1)  // 25600

typedef unsigned long long ull;

// Scratch (no cudaMalloc allowed -> __device__ globals)
__device__ float g_m1[M1 * ND];   // mean over S2 of hop-2 feats   [25600,256]
__device__ float g_m0[NB * ND];   // mean over S1 of hop-1 feats   [1024,256]
__device__ float g_g1[M1 * ND];   // layer-1 out, hop-1 set        [25600,256]
__device__ float g_g0[NB * ND];   // layer-1 out, batch set        [1024,256]
__device__ float g_gm[NB * ND];   // mean over S1 of g1            [1024,256]

// ---- packed dual-fp32 helpers (SASS FFMA2; only reachable via PTX) --------
__device__ __forceinline__ ull dup2(float x) {
    ull r; asm("mov.b64 %0, {%1, %1};" : "=l"(r) : "f"(x)); return r;
}
__device__ __forceinline__ void ffma2(ull& d, ull a, ull b) {
    asm("fma.rn.f32x2 %0, %1, %2, %0;" : "+l"(d) : "l"(a), "l"(b));
}
__device__ __forceinline__ float2 unpk2(ull v) {
    float2 r; asm("mov.b64 {%0, %1}, %2;" : "=f"(r.x), "=f"(r.y) : "l"(v));
    return r;
}

// ---------------------------------------------------------------------------
// Templated float4 gather-mean: dst[g,:] = (1/F)*sum_{s<F} src[row(g,s),:]
// 64 threads per group, ids preloaded -> F loads in flight (high MLP).
// ---------------------------------------------------------------------------
template<int F, bool HAS_IDS>
__device__ __forceinline__ void mean_body(
    const float* __restrict__ src, const int* __restrict__ ids,
    float* __restrict__ dst, int g)
{
    const int c = (threadIdx.x & 63) * 4;
    const long base = (long)g * F;
    int rows[F];
    #pragma unroll
    for (int s = 0; s < F; ++s)
        rows[s] = HAS_IDS ? ids[base + s] : (int)(base + s);
    float4 acc = make_float4(0.f, 0.f, 0.f, 0.f);
    #pragma unroll
    for (int s = 0; s < F; ++s) {
        float4 u = *(const float4*)&src[(size_t)rows[s] * ND + c];
        acc.x += u.x; acc.y += u.y; acc.z += u.z; acc.w += u.w;
    }
    constexpr float inv = 1.0f / (float)F;
    acc.x *= inv; acc.y *= inv; acc.z *= inv; acc.w *= inv;
    *(float4*)&dst[(size_t)g * ND + c] = acc;
}

__global__ void __launch_bounds__(256) means_kernel(
    const float* __restrict__ feat,
    const int* __restrict__ ids1, const int* __restrict__ ids2,
    float* __restrict__ m1, float* __restrict__ m0)
{
    const int sub = threadIdx.x >> 6;
    if (blockIdx.x < M1 / 4)
        mean_body<NS2, true>(feat, ids2, m1, blockIdx.x * 4 + sub);
    else
        mean_body<NS1, true>(feat, ids1, m0, (blockIdx.x - M1 / 4) * 4 + sub);
}

__global__ void __launch_bounds__(256) g1mean_kernel(
    const float* __restrict__ g1, float* __restrict__ gm)
{
    mean_body<NS1, false>(g1, nullptr, gm,
                          blockIdx.x * 4 + (threadIdx.x >> 6));
}

// ---------------------------------------------------------------------------
// 128x128 tile GEMM, BK=32, 256 threads, 8x8 micro-tile via FFMA2 (8 rows x
// 4 col-pairs of packed fp32). Register-staged global pipeline. A rows
// optionally gathered through ids.
// ---------------------------------------------------------------------------
template<bool HAS_IDS, bool RELU>
__device__ __forceinline__ void gemm128(
    float* __restrict__ As,              // smem [32][132]
    float* __restrict__ Bs,              // smem [32][128]
    const float* __restrict__ Asrc, const int* __restrict__ ids,
    const float* __restrict__ W, const float* __restrict__ bias,
    float* __restrict__ C, int colOff, int mbase)
{
    const int t  = threadIdx.x;
    const int kq = t >> 5;               // 0..7  (k quad: k base = 4*kq)
    const int ml = t & 31;               // m lane

    int arow4[4];
    #pragma unroll
    for (int i = 0; i < 4; ++i) {
        int m = ml + i * 32;
        arow4[i] = HAS_IDS ? ids[mbase + m] : (mbase + m);
    }
    const float* abase = Asrc + 4 * kq;
    const float* bptr  = W + (size_t)kq * NH + (t & 31) * 4;

    ull acc2[8][4];
    #pragma unroll
    for (int i = 0; i < 8; ++i)
        #pragma unroll
        for (int p = 0; p < 4; ++p) acc2[i][p] = 0ull;

    float4 areg[4], breg[4];
    #pragma unroll
    for (int i = 0; i < 4; ++i)
        areg[i] = *(const float4*)(abase + (size_t)arow4[i] * ND);
    #pragma unroll
    for (int p = 0; p < 4; ++p)
        breg[p] = *(const float4*)(bptr + (size_t)(p * 8) * NH);

    const int row0 = (t >> 4) * 8;
    const int col0 = (t & 15) * 8;

    #pragma unroll 1
    for (int c0 = 0; c0 < 8; ++c0) {
        // ---- stage regs -> smem ----
        #pragma unroll
        for (int i = 0; i < 4; ++i) {
            const int m = ml + i * 32;
            As[(4 * kq + 0) * 132 + m] = areg[i].x;
            As[(4 * kq + 1) * 132 + m] = areg[i].y;
            As[(4 * kq + 2) * 132 + m] = areg[i].z;
            As[(4 * kq + 3) * 132 + m] = areg[i].w;
        }
        #pragma unroll
        for (int p = 0; p < 4; ++p)
            *(float4*)&Bs[(kq + p * 8) * 128 + (t & 31) * 4] = breg[p];
        __syncthreads();

        // ---- prefetch next chunk ----
        if (c0 < 7) {
            const int koff = (c0 + 1) * 32;
            #pragma unroll
            for (int i = 0; i < 4; ++i)
                areg[i] = *(const float4*)(abase + (size_t)arow4[i] * ND + koff);
            #pragma unroll
            for (int p = 0; p < 4; ++p)
                breg[p] = *(const float4*)(bptr + (size_t)(koff + p * 8) * NH);
        }

        // ---- packed micro-kernel: 8 rows x 4 col-pairs ----
        #pragma unroll
        for (int k = 0; k < 32; ++k) {
            float4 a0 = *(const float4*)&As[k * 132 + row0];
            float4 a1 = *(const float4*)&As[k * 132 + row0 + 4];
            ulonglong2 q0 = *(const ulonglong2*)&Bs[k * 128 + col0];
            ulonglong2 q1 = *(const ulonglong2*)&Bs[k * 128 + col0 + 4];
            ull b2[4] = {q0.x, q0.y, q1.x, q1.y};
            float av[8] = {a0.x, a0.y, a0.z, a0.w, a1.x, a1.y, a1.z, a1.w};
            #pragma unroll
            for (int i = 0; i < 8; ++i) {
                ull ad = dup2(av[i]);
                #pragma unroll
                for (int p = 0; p < 4; ++p)
                    ffma2(acc2[i][p], ad, b2[p]);
            }
        }
        __syncthreads();
    }

    float bb[8];
    #pragma unroll
    for (int j = 0; j < 8; ++j) bb[j] = bias[col0 + j];

    #pragma unroll
    for (int i = 0; i < 8; ++i) {
        float v[8];
        #pragma unroll
        for (int p = 0; p < 4; ++p) {
            float2 u = unpk2(acc2[i][p]);
            v[2 * p] = u.x; v[2 * p + 1] = u.y;
        }
        #pragma unroll
        for (int j = 0; j < 8; ++j) {
            float x = v[j] + bb[j];
            v[j] = RELU ? fmaxf(x, 0.f) : x;
        }
        float* dst = &C[(size_t)(mbase + row0 + i) * ND + colOff + col0];
        *(float4*)(dst)     = make_float4(v[0], v[1], v[2], v[3]);
        *(float4*)(dst + 4) = make_float4(v[4], v[5], v[6], v[7]);
    }
}

// ---------------------------------------------------------------------------
// Layer 1: all four branch GEMMs. grid (208, 2).
// ---------------------------------------------------------------------------
__global__ void __launch_bounds__(256, 2) layer1_kernel(
    const float* __restrict__ feat,
    const int* __restrict__ ids0, const int* __restrict__ ids1,
    const float* __restrict__ m1, const float* __restrict__ m0,
    const float* __restrict__ Wx1, const float* __restrict__ bx1,
    const float* __restrict__ Wn1, const float* __restrict__ bn1,
    float* __restrict__ g1, float* __restrict__ g0)
{
    __shared__ float As[32 * 132];
    __shared__ float Bs[32 * 128];
    const int x = blockIdx.x;

    if (blockIdx.y == 0) {
        if (x < 200)
            gemm128<true, true>(As, Bs, feat, ids1, Wx1, bx1, g1, 0, x * 128);
        else
            gemm128<true, true>(As, Bs, feat, ids0, Wx1, bx1, g0, 0,
                                (x - 200) * 128);
    } else {
        if (x < 200)
            gemm128<false, true>(As, Bs, m1, nullptr, Wn1, bn1, g1, NH,
                                 x * 128);
        else
            gemm128<false, true>(As, Bs, m0, nullptr, Wn1, bn1, g0, NH,
                                 (x - 200) * 128);
    }
}

// ---------------------------------------------------------------------------
// Fused layer2 + head. grid 64, 16-row tiles. Packed FFMA2 micro-kernel.
// smem layout (floats): As0[32][20]@0, As1[32][20]@640, Bs[32][256]@1280,
// f0s[16][260]@1280 (alias), Ws[32][68]@1280+4608.
// ---------------------------------------------------------------------------
#define L2R 16
__global__ void __launch_bounds__(256) layer2_head_kernel(
    const float* __restrict__ g0, const float* __restrict__ gm,
    const float* __restrict__ Wx2, const float* __restrict__ bx2,
    const float* __restrict__ Wn2, const float* __restrict__ bn2,
    const float* __restrict__ Wfc, const float* __restrict__ bfc,
    float* __restrict__ out)
{
    __shared__ float sm[1280 + 8320];
    float* As0 = sm;                 // [32][20]
    float* As1 = sm + 640;           // [32][20]
    float* Bs  = sm + 1280;          // [32][256]
    float* f0s = sm + 1280;          // [16][260] (alias)
    float* Ws  = sm + 1280 + 4608;   // [32][68]

    const int t  = threadIdx.x;
    const int m0 = blockIdx.x * L2R;

    const int r0   = (t >> 5) * 2;       // 8 row-groups x 2 rows
    const int col0 = (t & 31) * 8;       // 32 col-groups x 8 cols

    const int tt   = t & 127;
    const int arow = tt & 15;
    const int akq  = tt >> 4;
    const float* Aglob = (t < 128) ? g0 : gm;
    float* Asm = (t < 128) ? As0 : As1;
    const float* aptr = Aglob + (size_t)(m0 + arow) * ND + 4 * akq;

    ull acc2[2][4];
    #pragma unroll
    for (int i = 0; i < 2; ++i)
        #pragma unroll
        for (int p = 0; p < 4; ++p) acc2[i][p] = 0ull;

    float4 areg = *(const float4*)(aptr);
    float4 breg[8];
    #pragma unroll
    for (int i = 0; i < 8; ++i) {
        int f4 = t + 256 * i;
        int k = f4 >> 6, n4 = (f4 & 63) * 4;
        const float* src = (n4 < 128) ? &Wx2[(size_t)k * NH + n4]
                                      : &Wn2[(size_t)k * NH + (n4 - 128)];
        breg[i] = *(const float4*)src;
    }

    const float* Asel = (col0 < 128) ? As0 : As1;

    #pragma unroll 1
    for (int c0 = 0; c0 < 8; ++c0) {
        Asm[(4 * akq + 0) * 20 + arow] = areg.x;
        Asm[(4 * akq + 1) * 20 + arow] = areg.y;
        Asm[(4 * akq + 2) * 20 + arow] = areg.z;
        Asm[(4 * akq + 3) * 20 + arow] = areg.w;
        #pragma unroll
        for (int i = 0; i < 8; ++i) {
            int f4 = t + 256 * i;
            int k = f4 >> 6, n4 = (f4 & 63) * 4;
            *(float4*)&Bs[k * 256 + n4] = breg[i];
        }
        __syncthreads();

        if (c0 < 7) {
            const int koff = (c0 + 1) * 32;
            areg = *(const float4*)(aptr + koff);
            #pragma unroll
            for (int i = 0; i < 8; ++i) {
                int f4 = t + 256 * i;
                int k = (f4 >> 6) + koff, n4 = (f4 & 63) * 4;
                const float* src = (n4 < 128)
                    ? &Wx2[(size_t)k * NH + n4]
                    : &Wn2[(size_t)k * NH + (n4 - 128)];
                breg[i] = *(const float4*)src;
            }
        }

        #pragma unroll
        for (int k = 0; k < 32; ++k) {
            float2 aa = *(const float2*)&Asel[k * 20 + r0];
            ulonglong2 q0 = *(const ulonglong2*)&Bs[k * 256 + col0];
            ulonglong2 q1 = *(const ulonglong2*)&Bs[k * 256 + col0 + 4];
            ull b2[4] = {q0.x, q0.y, q1.x, q1.y};
            ull ad0 = dup2(aa.x), ad1 = dup2(aa.y);
            #pragma unroll
            for (int p = 0; p < 4; ++p) {
                ffma2(acc2[0][p], ad0, b2[p]);
                ffma2(acc2[1][p], ad1, b2[p]);
            }
        }
        __syncthreads();
    }

    // ---- stage f0 tile (+bias) into smem ----
    #pragma unroll
    for (int i = 0; i < 2; ++i) {
        #pragma unroll
        for (int p = 0; p < 4; ++p) {
            float2 u = unpk2(acc2[i][p]);
            int n = col0 + 2 * p;
            float b0v = (n < 128) ? bx2[n] : bn2[n - 128];
            float b1v = (n + 1 < 128) ? bx2[n + 1] : bn2[n + 1 - 128];
            f0s[(r0 + i) * 260 + n]     = u.x + b0v;
            f0s[(r0 + i) * 260 + n + 1] = u.y + b1v;
        }
    }
    __syncthreads();

    // ---- head: out[16 x 64] = f0s @ Wfc + bfc ----
    const int hr0 = (t >> 5) * 2;
    const int hc0 = (t & 31) * 2;
    float hacc[2][2] = {{0.f, 0.f}, {0.f, 0.f}};

    #pragma unroll 1
    for (int k0 = 0; k0 < ND; k0 += 32) {
        #pragma unroll
        for (int i = 0; i < 2; ++i) {
            int f4 = t + 256 * i;
            int k = f4 >> 4, c4 = (f4 & 15) * 4;
            *(float4*)&Ws[k * 68 + c4] =
                *(const float4*)&Wfc[(size_t)(k0 + k) * NC + c4];
        }
        __syncthreads();
        #pragma unroll
        for (int k = 0; k < 32; ++k) {
            float a0 = f0s[hr0 * 260 + k0 + k];
            float a1 = f0s[(hr0 + 1) * 260 + k0 + k];
            float w0 = Ws[k * 68 + hc0];
            float w1 = Ws[k * 68 + hc0 + 1];
            hacc[0][0] = fmaf(a0, w0, hacc[0][0]);
            hacc[0][1] = fmaf(a0, w1, hacc[0][1]);
            hacc[1][0] = fmaf(a1, w0, hacc[1][0]);
            hacc[1][1] = fmaf(a1, w1, hacc[1][1]);
        }
        __syncthreads();
    }

    float bf0 = bfc[hc0], bf1 = bfc[hc0 + 1];
    out[(size_t)(m0 + hr0) * NC + hc0]         = hacc[0][0] + bf0;
    out[(size_t)(m0 + hr0) * NC + hc0 + 1]     = hacc[0][1] + bf1;
    out[(size_t)(m0 + hr0 + 1) * NC + hc0]     = hacc[1][0] + bf0;
    out[(size_t)(m0 + hr0 + 1) * NC + hc0 + 1] = hacc[1][1] + bf1;
}

// ---------------------------------------------------------------------------
extern "C" void kernel_launch(void* const* d_in, const int* in_sizes, int n_in,
                              void* d_out, int out_size)
{
    const int*   ids0 = (const int*)  d_in[0];
    const int*   ids1 = (const int*)  d_in[1];
    const int*   ids2 = (const int*)  d_in[2];
    const float* feat = (const float*)d_in[3];
    const float* Wx1  = (const float*)d_in[4];
    const float* bx1  = (const float*)d_in[5];
    const float* Wn1  = (const float*)d_in[6];
    const float* bn1  = (const float*)d_in[7];
    const float* Wx2  = (const float*)d_in[8];
    const float* bx2  = (const float*)d_in[9];
    const float* Wn2  = (const float*)d_in[10];
    const float* bn2  = (const float*)d_in[11];
    const float* Wfc  = (const float*)d_in[12];
    const float* bfc  = (const float*)d_in[13];
    float* out = (float*)d_out;

    float *m1, *m0, *g1, *g0, *gm;
    cudaGetSymbolAddress((void**)&m1, g_m1);
    cudaGetSymbolAddress((void**)&m0, g_m0);
    cudaGetSymbolAddress((void**)&g1, g_g1);
    cudaGetSymbolAddress((void**)&g0, g_g0);
    cudaGetSymbolAddress((void**)&gm, g_gm);

    // 1) hop-2 + hop-1 gather means
    means_kernel<<<M1 / 4 + NB / 4, 256>>>(feat, ids1, ids2, m1, m0);

    // 2) layer 1: all four branch GEMMs (packed FFMA2)
    layer1_kernel<<<dim3(208, 2), 256>>>(
        feat, ids0, ids1, m1, m0, Wx1, bx1, Wn1, bn1, g1, g0);

    // 3) mean over S1 of g1
    g1mean_kernel<<<NB / 4, 256>>>(g1, gm);

    // 4) fused layer 2 + head (packed FFMA2)
    layer2_head_kernel<<<NB / L2R, 256>>>(
        g0, gm, Wx2, bx2, Wn2, bn2, Wfc, bfc, out);
}

// round 6
// speedup vs baseline: 3.0168x; 1.0785x over previous
#include <cuda_runtime.h>
#include <cuda_bf16.h>

// Problem constants (fixed by the reference)
#define NB   1024      // batch
#define NS1  25        // hop-1 fanout
#define NS2  10        // hop-2 fanout
#define ND   256       // feature dim
#define NH   128       // per-branch hidden
#define NC   64        // classes
#define M1   (NB*S1_)  // (defined below)
#define S1_  25
#undef  M1
#define M1   (NB*NS1)  // 25600
#define NMEAN (M1/4 + NB/4)   // 6656 mean blocks

typedef unsigned long long ull;

// Scratch (no cudaMalloc allowed -> __device__ globals)
__device__ float g_m1[M1 * ND];   // mean over S2 of hop-2 feats   [25600,256]
__device__ float g_m0[NB * ND];   // mean over S1 of hop-1 feats   [1024,256]
__device__ float g_g1[M1 * ND];   // layer-1 out, hop-1 set        [25600,256]
__device__ float g_g0[NB * ND];   // layer-1 out, batch set        [1024,256]
__device__ float g_gm[NB * ND];   // mean over S1 of g1            [1024,256]
__device__ float g_Wc[512 * NC];  // collapsed layer2*head weights [512,64]
__device__ float g_bc[NC];        // collapsed bias                [64]

// ---- packed dual-fp32 helpers (SASS FFMA2; only reachable via PTX) --------
__device__ __forceinline__ ull dup2(float x) {
    ull r; asm("mov.b64 %0, {%1, %1};" : "=l"(r) : "f"(x)); return r;
}
__device__ __forceinline__ void ffma2(ull& d, ull a, ull b) {
    asm("fma.rn.f32x2 %0, %1, %2, %0;" : "+l"(d) : "l"(a), "l"(b));
}
__device__ __forceinline__ float2 unpk2(ull v) {
    float2 r; asm("mov.b64 {%0, %1}, %2;" : "=f"(r.x), "=f"(r.y) : "l"(v));
    return r;
}

// ---------------------------------------------------------------------------
// Templated float4 gather-mean: dst[g,:] = (1/F)*sum_{s<F} src[row(g,s),:]
// ---------------------------------------------------------------------------
template<int F, bool HAS_IDS>
__device__ __forceinline__ void mean_body(
    const float* __restrict__ src, const int* __restrict__ ids,
    float* __restrict__ dst, int g)
{
    const int c = (threadIdx.x & 63) * 4;
    const long base = (long)g * F;
    int rows[F];
    #pragma unroll
    for (int s = 0; s < F; ++s)
        rows[s] = HAS_IDS ? ids[base + s] : (int)(base + s);
    float4 acc = make_float4(0.f, 0.f, 0.f, 0.f);
    #pragma unroll
    for (int s = 0; s < F; ++s) {
        float4 u = *(const float4*)&src[(size_t)rows[s] * ND + c];
        acc.x += u.x; acc.y += u.y; acc.z += u.z; acc.w += u.w;
    }
    constexpr float inv = 1.0f / (float)F;
    acc.x *= inv; acc.y *= inv; acc.z *= inv; acc.w *= inv;
    *(float4*)&dst[(size_t)g * ND + c] = acc;
}

// ---------------------------------------------------------------------------
// means + weight-collapse precompute, one launch. Grid = NMEAN + 33.
//   blocks [0, M1/4):        m1 = mean10(feat[ids2])
//   blocks [M1/4, NMEAN):    m0 = mean25(feat[ids1])
//   blocks [NMEAN, NMEAN+32): Wc[512,64] (16 rows each)
//   block  NMEAN+32:         bc[64]
// ---------------------------------------------------------------------------
__global__ void __launch_bounds__(256) means_kernel(
    const float* __restrict__ feat,
    const int* __restrict__ ids1, const int* __restrict__ ids2,
    const float* __restrict__ Wx2, const float* __restrict__ bx2,
    const float* __restrict__ Wn2, const float* __restrict__ bn2,
    const float* __restrict__ Wfc, const float* __restrict__ bfc,
    float* __restrict__ m1, float* __restrict__ m0,
    float* __restrict__ Wc, float* __restrict__ bc)
{
    const int bx = blockIdx.x;
    const int t  = threadIdx.x;
    if (bx < M1 / 4) {
        mean_body<NS2, true>(feat, ids2, m1, bx * 4 + (t >> 6));
    } else if (bx < NMEAN) {
        mean_body<NS1, true>(feat, ids1, m0, (bx - M1 / 4) * 4 + (t >> 6));
    } else if (bx < NMEAN + 32) {
        // Wc rows [R0, R0+16): Wc_top = Wx2@Wfc[0:128], Wc_bot = Wn2@Wfc[128:]
        const int R0 = (bx - NMEAN) * 16;
        const int c  = t & 63;
        const int rg = t >> 6;                 // 4 groups x 4 rows
        const bool top = (R0 < 256);
        const float* W2   = top ? Wx2 : Wn2;
        const float* WfcH = Wfc + (top ? 0 : 128 * NC);
        const int rbase = (top ? R0 : R0 - 256) + rg * 4;
        float acc[4] = {0.f, 0.f, 0.f, 0.f};
        #pragma unroll 8
        for (int k = 0; k < 128; ++k) {
            float w = WfcH[(size_t)k * NC + c];
            #pragma unroll
            for (int i = 0; i < 4; ++i)
                acc[i] = fmaf(W2[(size_t)(rbase + i) * NH + k], w, acc[i]);
        }
        #pragma unroll
        for (int i = 0; i < 4; ++i)
            Wc[(size_t)(R0 + rg * 4 + i) * NC + c] = acc[i];
    } else {
        // bc[c] = bfc[c] + bx2 @ Wfc_top[:,c] + bn2 @ Wfc_bot[:,c]
        if (t < NC) {
            float acc = bfc[t];
            #pragma unroll 8
            for (int k = 0; k < 128; ++k) {
                acc = fmaf(bx2[k], Wfc[(size_t)k * NC + t], acc);
                acc = fmaf(bn2[k], Wfc[(size_t)(128 + k) * NC + t], acc);
            }
            bc[t] = acc;
        }
    }
}

// g1 mean (1024 groups, F=25, dense rows)
__global__ void __launch_bounds__(256) g1mean_kernel(
    const float* __restrict__ g1, float* __restrict__ gm)
{
    mean_body<NS1, false>(g1, nullptr, gm,
                          blockIdx.x * 4 + (threadIdx.x >> 6));
}

// ---------------------------------------------------------------------------
// 128x128 tile GEMM, BK=32, 256 threads, 8x8 micro-tile via FFMA2.
// Register-staged global pipeline. A rows optionally gathered through ids.
// ---------------------------------------------------------------------------
template<bool HAS_IDS, bool RELU>
__device__ __forceinline__ void gemm128(
    float* __restrict__ As,              // smem [32][132]
    float* __restrict__ Bs,              // smem [32][128]
    const float* __restrict__ Asrc, const int* __restrict__ ids,
    const float* __restrict__ W, const float* __restrict__ bias,
    float* __restrict__ C, int colOff, int mbase)
{
    const int t  = threadIdx.x;
    const int kq = t >> 5;               // 0..7  (k quad: k base = 4*kq)
    const int ml = t & 31;               // m lane

    int arow4[4];
    #pragma unroll
    for (int i = 0; i < 4; ++i) {
        int m = ml + i * 32;
        arow4[i] = HAS_IDS ? ids[mbase + m] : (mbase + m);
    }
    const float* abase = Asrc + 4 * kq;
    const float* bptr  = W + (size_t)kq * NH + (t & 31) * 4;

    ull acc2[8][4];
    #pragma unroll
    for (int i = 0; i < 8; ++i)
        #pragma unroll
        for (int p = 0; p < 4; ++p) acc2[i][p] = 0ull;

    float4 areg[4], breg[4];
    #pragma unroll
    for (int i = 0; i < 4; ++i)
        areg[i] = *(const float4*)(abase + (size_t)arow4[i] * ND);
    #pragma unroll
    for (int p = 0; p < 4; ++p)
        breg[p] = *(const float4*)(bptr + (size_t)(p * 8) * NH);

    const int row0 = (t >> 4) * 8;
    const int col0 = (t & 15) * 8;

    #pragma unroll 1
    for (int c0 = 0; c0 < 8; ++c0) {
        #pragma unroll
        for (int i = 0; i < 4; ++i) {
            const int m = ml + i * 32;
            As[(4 * kq + 0) * 132 + m] = areg[i].x;
            As[(4 * kq + 1) * 132 + m] = areg[i].y;
            As[(4 * kq + 2) * 132 + m] = areg[i].z;
            As[(4 * kq + 3) * 132 + m] = areg[i].w;
        }
        #pragma unroll
        for (int p = 0; p < 4; ++p)
            *(float4*)&Bs[(kq + p * 8) * 128 + (t & 31) * 4] = breg[p];
        __syncthreads();

        if (c0 < 7) {
            const int koff = (c0 + 1) * 32;
            #pragma unroll
            for (int i = 0; i < 4; ++i)
                areg[i] = *(const float4*)(abase + (size_t)arow4[i] * ND + koff);
            #pragma unroll
            for (int p = 0; p < 4; ++p)
                breg[p] = *(const float4*)(bptr + (size_t)(koff + p * 8) * NH);
        }

        #pragma unroll
        for (int k = 0; k < 32; ++k) {
            float4 a0 = *(const float4*)&As[k * 132 + row0];
            float4 a1 = *(const float4*)&As[k * 132 + row0 + 4];
            ulonglong2 q0 = *(const ulonglong2*)&Bs[k * 128 + col0];
            ulonglong2 q1 = *(const ulonglong2*)&Bs[k * 128 + col0 + 4];
            ull b2[4] = {q0.x, q0.y, q1.x, q1.y};
            float av[8] = {a0.x, a0.y, a0.z, a0.w, a1.x, a1.y, a1.z, a1.w};
            #pragma unroll
            for (int i = 0; i < 8; ++i) {
                ull ad = dup2(av[i]);
                #pragma unroll
                for (int p = 0; p < 4; ++p)
                    ffma2(acc2[i][p], ad, b2[p]);
            }
        }
        __syncthreads();
    }

    float bb[8];
    #pragma unroll
    for (int j = 0; j < 8; ++j) bb[j] = bias[col0 + j];

    #pragma unroll
    for (int i = 0; i < 8; ++i) {
        float v[8];
        #pragma unroll
        for (int p = 0; p < 4; ++p) {
            float2 u = unpk2(acc2[i][p]);
            v[2 * p] = u.x; v[2 * p + 1] = u.y;
        }
        #pragma unroll
        for (int j = 0; j < 8; ++j) {
            float x = v[j] + bb[j];
            v[j] = RELU ? fmaxf(x, 0.f) : x;
        }
        float* dst = &C[(size_t)(mbase + row0 + i) * ND + colOff + col0];
        *(float4*)(dst)     = make_float4(v[0], v[1], v[2], v[3]);
        *(float4*)(dst + 4) = make_float4(v[4], v[5], v[6], v[7]);
    }
}

// ---------------------------------------------------------------------------
// Layer 1: all four branch GEMMs. grid (208, 2).
// ---------------------------------------------------------------------------
__global__ void __launch_bounds__(256, 2) layer1_kernel(
    const float* __restrict__ feat,
    const int* __restrict__ ids0, const int* __restrict__ ids1,
    const float* __restrict__ m1, const float* __restrict__ m0,
    const float* __restrict__ Wx1, const float* __restrict__ bx1,
    const float* __restrict__ Wn1, const float* __restrict__ bn1,
    float* __restrict__ g1, float* __restrict__ g0)
{
    __shared__ float As[32 * 132];
    __shared__ float Bs[32 * 128];
    const int x = blockIdx.x;

    if (blockIdx.y == 0) {
        if (x < 200)
            gemm128<true, true>(As, Bs, feat, ids1, Wx1, bx1, g1, 0, x * 128);
        else
            gemm128<true, true>(As, Bs, feat, ids0, Wx1, bx1, g0, 0,
                                (x - 200) * 128);
    } else {
        if (x < 200)
            gemm128<false, true>(As, Bs, m1, nullptr, Wn1, bn1, g1, NH,
                                 x * 128);
        else
            gemm128<false, true>(As, Bs, m0, nullptr, Wn1, bn1, g0, NH,
                                 (x - 200) * 128);
    }
}

// ---------------------------------------------------------------------------
// Final collapsed GEMM: out[1024,64] = [g0 | gm] @ Wc[512,64] + bc.
// grid 128, 8 rows per CTA. A staged once in smem; W chunks reg-prefetched.
// ---------------------------------------------------------------------------
__global__ void __launch_bounds__(256) final_kernel(
    const float* __restrict__ g0, const float* __restrict__ gm,
    const float* __restrict__ Wc, const float* __restrict__ bc,
    float* __restrict__ out)
{
    __shared__ float As[8 * 516];      // [row][k 0..511], pad 4
    __shared__ float Ws[64 * 68];      // [k][c], pad 4

    const int t  = threadIdx.x;
    const int m0 = blockIdx.x * 8;

    // ---- stage A: 8 rows x 512 k (g0 for k<256, gm for k>=256) ----
    #pragma unroll
    for (int i = 0; i < 4; ++i) {
        int s = t + 256 * i;                 // 1024 float4 slots
        int row = s >> 7, k4 = (s & 127) * 4;
        const float* src = (k4 < 256)
            ? &g0[(size_t)(m0 + row) * ND + k4]
            : &gm[(size_t)(m0 + row) * ND + (k4 - 256)];
        *(float4*)&As[row * 516 + k4] = *(const float4*)src;
    }

    // ---- prefetch W chunk 0 ----
    float4 breg[4];
    #pragma unroll
    for (int i = 0; i < 4; ++i) {
        int s = t + 256 * i;                 // 1024 float4 slots
        int kk = s >> 4, c4 = (s & 15) * 4;
        breg[i] = *(const float4*)&Wc[(size_t)kk * NC + c4];
    }
    __syncthreads();

    const int c  = t & 63;
    const int r0 = (t >> 6) * 2;             // 4 groups x 2 rows
    float acc0 = 0.f, acc1 = 0.f;

    #pragma unroll 1
    for (int j = 0; j < 8; ++j) {
        #pragma unroll
        for (int i = 0; i < 4; ++i) {
            int s = t + 256 * i;
            int kk = s >> 4, c4 = (s & 15) * 4;
            *(float4*)&Ws[kk * 68 + c4] = breg[i];
        }
        __syncthreads();

        if (j < 7) {
            #pragma unroll
            for (int i = 0; i < 4; ++i) {
                int s = t + 256 * i;
                int kk = (s >> 4) + (j + 1) * 64, c4 = (s & 15) * 4;
                breg[i] = *(const float4*)&Wc[(size_t)kk * NC + c4];
            }
        }

        const float* a0p = &As[r0 * 516 + j * 64];
        const float* a1p = &As[(r0 + 1) * 516 + j * 64];
        #pragma unroll
        for (int k = 0; k < 64; ++k) {
            float w = Ws[k * 68 + c];
            acc0 = fmaf(a0p[k], w, acc0);
            acc1 = fmaf(a1p[k], w, acc1);
        }
        __syncthreads();
    }

    float b = bc[c];
    out[(size_t)(m0 + r0) * NC + c]     = acc0 + b;
    out[(size_t)(m0 + r0 + 1) * NC + c] = acc1 + b;
}

// ---------------------------------------------------------------------------
extern "C" void kernel_launch(void* const* d_in, const int* in_sizes, int n_in,
                              void* d_out, int out_size)
{
    const int*   ids0 = (const int*)  d_in[0];
    const int*   ids1 = (const int*)  d_in[1];
    const int*   ids2 = (const int*)  d_in[2];
    const float* feat = (const float*)d_in[3];
    const float* Wx1  = (const float*)d_in[4];
    const float* bx1  = (const float*)d_in[5];
    const float* Wn1  = (const float*)d_in[6];
    const float* bn1  = (const float*)d_in[7];
    const float* Wx2  = (const float*)d_in[8];
    const float* bx2  = (const float*)d_in[9];
    const float* Wn2  = (const float*)d_in[10];
    const float* bn2  = (const float*)d_in[11];
    const float* Wfc  = (const float*)d_in[12];
    const float* bfc  = (const float*)d_in[13];
    float* out = (float*)d_out;

    float *m1, *m0, *g1, *g0, *gm, *Wc, *bc;
    cudaGetSymbolAddress((void**)&m1, g_m1);
    cudaGetSymbolAddress((void**)&m0, g_m0);
    cudaGetSymbolAddress((void**)&g1, g_g1);
    cudaGetSymbolAddress((void**)&g0, g_g0);
    cudaGetSymbolAddress((void**)&gm, g_gm);
    cudaGetSymbolAddress((void**)&Wc, g_Wc);
    cudaGetSymbolAddress((void**)&bc, g_bc);

    // 1) gather means + collapsed-weight precompute (concurrent blocks)
    means_kernel<<<NMEAN + 33, 256>>>(
        feat, ids1, ids2, Wx2, bx2, Wn2, bn2, Wfc, bfc, m1, m0, Wc, bc);

    // 2) layer 1: all four branch GEMMs (packed FFMA2)
    layer1_kernel<<<dim3(208, 2), 256>>>(
        feat, ids0, ids1, m1, m0, Wx1, bx1, Wn1, bn1, g1, g0);

    // 3) mean over S1 of g1
    g1mean_kernel<<<NB / 4, 256>>>(g1, gm);

    // 4) collapsed layer2+head GEMM
    final_kernel<<<NB / 8, 256>>>(g0, gm, Wc, bc, out);
}